// round 13
// baseline (speedup 1.0000x reference)
#include <cuda_runtime.h>
#include <cuda_bf16.h>
#include <cuda_fp16.h>
#include <math.h>
#include <stdint.h>

#define NH   16
#define NKV  4
#define HD   128
#define SMAX 2048
#define KDIM 2048

// ---------------- scratch (device globals; no allocation allowed) ----------
__device__ __align__(256) __half g_Ah[SMAX * KDIM];
__device__ __align__(256) __half g_Bh[3072 * KDIM];
__device__ __align__(256) __half h_Q[SMAX * NH * HD];
__device__ __align__(256) __half h_K[SMAX * NKV * HD];
__device__ __align__(256) __half h_V[SMAX * NKV * HD];
__device__ __align__(256) float2 g_rope[SMAX * 64];

#define WSCALE 256.0f
#define INVW   0.00390625f

// ---------------- helpers --------------------------------------------------
__device__ __forceinline__ uint32_t smem_u32(const void* p) {
    uint32_t a;
    asm("{ .reg .u64 t; cvta.to.shared.u64 t, %1; cvt.u32.u64 %0, t; }"
        : "=r"(a) : "l"(p));
    return a;
}
__device__ __forceinline__ uint32_t h2_as_u32(__half2 h) {
    return *reinterpret_cast<uint32_t*>(&h);
}
__device__ __forceinline__ void ldm_x4(uint32_t* r, uint32_t addr) {
    asm volatile("ldmatrix.sync.aligned.m8n8.x4.shared.b16 {%0,%1,%2,%3}, [%4];"
                 : "=r"(r[0]), "=r"(r[1]), "=r"(r[2]), "=r"(r[3]) : "r"(addr));
}
__device__ __forceinline__ void ldm_x4_t(uint32_t* r, uint32_t addr) {
    asm volatile("ldmatrix.sync.aligned.m8n8.x4.trans.shared.b16 {%0,%1,%2,%3}, [%4];"
                 : "=r"(r[0]), "=r"(r[1]), "=r"(r[2]), "=r"(r[3]) : "r"(addr));
}
__device__ __forceinline__ void mma_f16(float* d, const uint32_t* a,
                                        uint32_t b0, uint32_t b1) {
    asm volatile(
        "mma.sync.aligned.m16n8k16.row.col.f32.f16.f16.f32 "
        "{%0,%1,%2,%3}, {%4,%5,%6,%7}, {%8,%9}, {%0,%1,%2,%3};"
        : "+f"(d[0]), "+f"(d[1]), "+f"(d[2]), "+f"(d[3])
        : "r"(a[0]), "r"(a[1]), "r"(a[2]), "r"(a[3]), "r"(b0), "r"(b1));
}
__device__ __forceinline__ void cp_async16(uint32_t dst, const void* src) {
    asm volatile("cp.async.cg.shared.global [%0], [%1], 16;"
                 :: "r"(dst), "l"(src) : "memory");
}
#define CP_COMMIT() asm volatile("cp.async.commit_group;" ::: "memory")
#define CP_WAIT0()  asm volatile("cp.async.wait_group 0;" ::: "memory")
#define CP_WAIT1()  asm volatile("cp.async.wait_group 1;" ::: "memory")

// ---------------------------------------------------------------------------
// fp16 GEMM via mma.sync, templated on CTA N-tile (at HMMA f32-accum roofline).
//   BN=64 : 128 threads (4 warps, 2x2 of 64x32), 3 CTAs/SM  (QKV)
//   BN=128: 256 threads (8 warps, 2x4 of 64x32), 2 CTAs/SM  (Wo)
// ---------------------------------------------------------------------------
#define NC (KDIM / 64)

template <int BN, int NTHREADS, int MINCTA>
__global__ __launch_bounds__(NTHREADS, MINCTA) void gemm_mma(
    float* __restrict__ C, int N, int qkv)
{
    constexpr int STAGEB = 16384 + BN * 128;
    constexpr int OFF_B  = 16384;
    extern __shared__ char smem[];
    const uint32_t sb = smem_u32(smem);
    const int tid = threadIdx.x, lane = tid & 31, wid = tid >> 5;
    const int m0 = blockIdx.y * 128, n0 = blockIdx.x * BN;
    const int wm = (BN == 64) ? (wid >> 1) * 64 : (wid >> 2) * 64;
    const int wn = (BN == 64) ? (wid & 1) * 32  : (wid & 3) * 32;

    auto load_chunk = [&](int c, int buf) {
        uint32_t base = sb + buf * STAGEB;
#pragma unroll
        for (int it = 0; it < 16384 / (16 * NTHREADS); it++) {
            int idx = tid + it * NTHREADS;
            int row = idx >> 3, ch = idx & 7;
            cp_async16(base + row * 128 + ((ch ^ (row & 7)) << 4),
                       g_Ah + (size_t)(m0 + row) * KDIM + c * 64 + ch * 8);
        }
#pragma unroll
        for (int it = 0; it < (BN * 128) / (16 * NTHREADS); it++) {
            int idx = tid + it * NTHREADS;
            int row = idx >> 3, ch = idx & 7;
            cp_async16(base + OFF_B + row * 128 + ((ch ^ (row & 7)) << 4),
                       g_Bh + (size_t)(n0 + row) * KDIM + c * 64 + ch * 8);
        }
        CP_COMMIT();
    };

    const int arow = wm + (lane & 15);
    const int cA   = lane >> 4;
    const int brow = wn + ((lane >> 4) << 3) + (lane & 7);
    const int cB   = (lane >> 3) & 1;

    float d[4][4][4];
#pragma unroll
    for (int i = 0; i < 4; i++)
#pragma unroll
        for (int j = 0; j < 4; j++)
#pragma unroll
            for (int k = 0; k < 4; k++) d[i][j][k] = 0.f;

    load_chunk(0, 0);
    load_chunk(1, 1);

    for (int c = 0; c < NC; c++) {
        if (c < NC - 1) CP_WAIT1(); else CP_WAIT0();
        __syncthreads();
        if (c + 2 < NC) load_chunk(c + 2, (c + 2) % 3);

        const uint32_t base = sb + (c % 3) * STAGEB;
#pragma unroll
        for (int ks = 0; ks < 4; ks++) {
            uint32_t a[4][4], b[2][4];
#pragma unroll
            for (int mt = 0; mt < 4; mt++) {
                int row = arow + mt * 16;
                ldm_x4(a[mt], base + row * 128 + (((ks * 2 + cA) ^ (row & 7)) << 4));
            }
#pragma unroll
            for (int np = 0; np < 2; np++) {
                int row = brow + np * 16;
                ldm_x4(b[np], base + OFF_B + row * 128 +
                              (((ks * 2 + cB) ^ (row & 7)) << 4));
            }
#pragma unroll
            for (int mt = 0; mt < 4; mt++)
#pragma unroll
                for (int np = 0; np < 2; np++)
#pragma unroll
                    for (int s = 0; s < 2; s++)
                        mma_f16(d[mt][np * 2 + s], a[mt],
                                b[np][2 * s], b[np][2 * s + 1]);
        }
        __syncthreads();
    }

    const int colb = (lane & 3) * 2;
    if (!qkv) {
#pragma unroll
        for (int mt = 0; mt < 4; mt++) {
            int r = m0 + wm + mt * 16 + (lane >> 2);
#pragma unroll
            for (int nt = 0; nt < 4; nt++) {
                int col = n0 + wn + nt * 8 + colb;
                *(float2*)(C + (size_t)r * N + col) =
                    make_float2(d[mt][nt][0] * INVW, d[mt][nt][1] * INVW);
                *(float2*)(C + (size_t)(r + 8) * N + col) =
                    make_float2(d[mt][nt][2] * INVW, d[mt][nt][3] * INVW);
            }
        }
    } else {
        const int mode = (n0 < 2048) ? 0 : (n0 < 2560 ? 1 : 2);
        // Q scale includes 1/sqrt(hd) * log2(e) so attention can use exp2f
        const float qs = 0.0883883476483184f * 1.4426950408889634f * INVW;
#pragma unroll
        for (int mt = 0; mt < 4; mt++) {
            int r = m0 + wm + mt * 16 + (lane >> 2);
#pragma unroll
            for (int nt = 0; nt < 4; nt++) {
                int col = n0 + wn + nt * 8 + colb;
                float c00 = d[mt][nt][0], c01 = d[mt][nt][1];
                float c10 = d[mt][nt][2], c11 = d[mt][nt][3];
                if (mode == 2) {
                    int cv = col - 2560;
                    *(__half2*)(h_V + (size_t)r * 512 + cv) =
                        __floats2half2_rn(c00 * INVW, c01 * INVW);
                    *(__half2*)(h_V + (size_t)(r + 8) * 512 + cv) =
                        __floats2half2_rn(c10 * INVW, c11 * INVW);
                } else {
                    int cl = (mode == 0) ? col : col - 2048;
                    int i = (cl & 127) >> 1;
                    float2 t0 = g_rope[r * 64 + i];
                    float2 t1 = g_rope[(r + 8) * 64 + i];
                    float s = (mode == 0) ? qs : INVW;
                    float o00 = (c00 * t0.x - c01 * t0.y) * s;
                    float o01 = (c00 * t0.y + c01 * t0.x) * s;
                    float o10 = (c10 * t1.x - c11 * t1.y) * s;
                    float o11 = (c10 * t1.y + c11 * t1.x) * s;
                    if (mode == 0) {
                        *(__half2*)(h_Q + (size_t)r * 2048 + cl)       = __floats2half2_rn(o00, o01);
                        *(__half2*)(h_Q + (size_t)(r + 8) * 2048 + cl) = __floats2half2_rn(o10, o11);
                    } else {
                        *(__half2*)(h_K + (size_t)r * 512 + cl)       = __floats2half2_rn(o00, o01);
                        *(__half2*)(h_K + (size_t)(r + 8) * 512 + cl) = __floats2half2_rn(o10, o11);
                    }
                }
            }
        }
    }
}

// ---------------------------------------------------------------------------
// conversions
// ---------------------------------------------------------------------------
__global__ void cvt_h(const float* __restrict__ in, __half* __restrict__ out, int n4)
{
    int i = blockIdx.x * blockDim.x + threadIdx.x;
    if (i >= n4) return;
    float4 v = ((const float4*)in)[i];
    uint2 u;
    u.x = h2_as_u32(__floats2half2_rn(v.x, v.y));
    u.y = h2_as_u32(__floats2half2_rn(v.z, v.w));
    ((uint2*)out)[i] = u;
}

__global__ void cvt_T_h(const float* __restrict__ W, __half* __restrict__ out,
                        int K, int N)
{
    __shared__ float t[32][33];
    int x = blockIdx.x * 32 + threadIdx.x;
    int y = blockIdx.y * 32 + threadIdx.y;
#pragma unroll
    for (int j = 0; j < 32; j += 8)
        t[threadIdx.y + j][threadIdx.x] = W[(size_t)(y + j) * N + x];
    __syncthreads();
    int x2 = blockIdx.y * 32 + threadIdx.x;
    int y2 = blockIdx.x * 32 + threadIdx.y;
#pragma unroll
    for (int j = 0; j < 32; j += 8)
        out[(size_t)(y2 + j) * K + x2] = __float2half_rn(t[threadIdx.x][threadIdx.y + j] * WSCALE);
}

__global__ void cvt_T_h3(const float* __restrict__ Wq, const float* __restrict__ Wk,
                         const float* __restrict__ Wv)
{
    __shared__ float t[32][33];
    int bc = blockIdx.x * 32;
    const float* W; int n0, Nw;
    if (bc < 2048)      { W = Wq; n0 = 0;    Nw = 2048; }
    else if (bc < 2560) { W = Wk; n0 = 2048; Nw = 512;  }
    else                { W = Wv; n0 = 2560; Nw = 512;  }
    int x = bc - n0 + threadIdx.x;
    int y = blockIdx.y * 32 + threadIdx.y;
#pragma unroll
    for (int j = 0; j < 32; j += 8)
        t[threadIdx.y + j][threadIdx.x] = W[(size_t)(y + j) * Nw + x];
    __syncthreads();
    int x2 = blockIdx.y * 32 + threadIdx.x;
    int y2 = bc + threadIdx.y;
#pragma unroll
    for (int j = 0; j < 32; j += 8)
        g_Bh[(size_t)(y2 + j) * KDIM + x2] =
            __float2half_rn(t[threadIdx.x][threadIdx.y + j] * WSCALE);
}

__global__ void rope_tab(const int* __restrict__ pos, int S)
{
    int idx = blockIdx.x * blockDim.x + threadIdx.x;
    if (idx >= S * 64) return;
    int i = idx & 63, s = idx >> 6;
    float freq = exp2f(-(float)(2 * i) * (1.0f / 128.0f) * 13.287712379549449f);
    float ang = (float)pos[s] * freq;
    float sn, cs;
    sincosf(ang, &sn, &cs);
    g_rope[idx] = make_float2(cs, sn);
}

// ---------------------------------------------------------------------------
// fp16 mma.sync flash attention (base-2 softmax), 2 heads per CTA (GQA pair
// shares K/V smem). 256 threads / 8 warps: warps 0-3 head 2y, 4-7 head 2y+1.
// BQ=64 per head, KV tiles of 64. Q(h0) staged in K-buf1, Q(h1) in V-buf1.
// 2 CTAs/SM; grid 256 CTAs = single wave. Epilogue writes fp16 A to g_Ah.
// ---------------------------------------------------------------------------
#define ATSTR 272
#define AT_KB 17408
#define AT_V  34816
#define AT_MC 69632
#define AT_SMEM 70144

__global__ __launch_bounds__(256, 2) void attn_mma(
    const int* __restrict__ amask, const int* __restrict__ segs)
{
    extern __shared__ char sm[];
    const uint32_t sb = smem_u32(sm);
    const int tid = threadIdx.x, lane = tid & 31, wid = tid >> 5;
    const int hw = wid >> 2;                 // head select within CTA
    const int wq = wid & 3;                  // q-row block
    const int h  = blockIdx.y * 2 + hw;
    const int qb = (int)gridDim.x - 1 - (int)blockIdx.x;   // long blocks first
    const int q0 = qb * 64;
    const int kvh = blockIdx.y >> 1;
    const int ntile = qb + 1;

    auto prefetch = [&](int t) {
        int k0 = t * 64;
        int buf = t & 1;
#pragma unroll
        for (int it = 0; it < 4; it++) {
            int idx = tid + it * 256;
            int row = idx >> 4, ch = idx & 15;
            cp_async16(sb + buf * AT_KB + row * ATSTR + ch * 16,
                       h_K + ((size_t)(k0 + row) * NKV + kvh) * HD + ch * 8);
            cp_async16(sb + AT_V + buf * AT_KB + row * ATSTR + ch * 16,
                       h_V + ((size_t)(k0 + row) * NKV + kvh) * HD + ch * 8);
        }
        if (tid < 64) {
            int a = amask[k0 + tid];
            ((int*)(sm + AT_MC))[buf * 64 + tid] =
                (a > 0) ? segs[k0 + tid] : 0x7fffffff;
        }
        CP_COMMIT();
    };

    // prologue: Q tiles for both heads (into K-buf1 / V-buf1) + tile 0
#pragma unroll
    for (int it = 0; it < 8; it++) {
        int idx = tid + it * 256;            // 0..2047
        int hsel = idx >> 10;                // 0/1
        int row  = (idx >> 4) & 63;
        int ch   = idx & 15;
        uint32_t dst = sb + (hsel ? (AT_V + AT_KB) : AT_KB) + row * ATSTR + ch * 16;
        cp_async16(dst, h_Q + ((size_t)(q0 + row) * NH + blockIdx.y * 2 + hsel) * HD + ch * 8);
    }
    prefetch(0);
    CP_WAIT0();
    __syncthreads();

    uint32_t qf[8][4];
    {
        uint32_t qbase = sb + (hw ? (AT_V + AT_KB) : AT_KB);
#pragma unroll
        for (int ks = 0; ks < 8; ks++) {
            uint32_t addr = qbase + (wq * 16 + (lane & 15)) * ATSTR +
                            (ks * 16 + (lane >> 4) * 8) * 2;
            ldm_x4(qf[ks], addr);
        }
    }
    __syncthreads();   // all warps consumed Q before prefetch(1) overwrites

    const int qr0 = q0 + wq * 16 + (lane >> 2);
    const int qr1 = qr0 + 8;
    const int qseg0 = segs[qr0];
    const int qseg1 = segs[qr1];
    const int colb = (lane & 3) * 2;

    float o[16][4];
#pragma unroll
    for (int j = 0; j < 16; j++)
#pragma unroll
        for (int k = 0; k < 4; k++) o[j][k] = 0.f;
    float m0 = -1e30f, m1 = -1e30f, l0 = 0.f, l1 = 0.f;

    for (int t = 0; t < ntile; t++) {
        const int k0 = t * 64;
        const int buf = t & 1;
        if (t + 1 < ntile) { prefetch(t + 1); CP_WAIT1(); }
        else               { CP_WAIT0(); }
        __syncthreads();

        float sf[8][4];
#pragma unroll
        for (int j = 0; j < 8; j++)
#pragma unroll
            for (int k = 0; k < 4; k++) sf[j][k] = 0.f;

        const uint32_t kb = sb + buf * AT_KB;
#pragma unroll
        for (int ks = 0; ks < 8; ks++) {
            uint32_t bk[4][4];
#pragma unroll
            for (int np = 0; np < 4; np++) {
                uint32_t addr = kb + (np * 16 + ((lane >> 4) << 3) + (lane & 7)) * ATSTR +
                                (ks * 16 + ((lane >> 3) & 1) * 8) * 2;
                ldm_x4(bk[np], addr);
            }
#pragma unroll
            for (int np = 0; np < 4; np++)
#pragma unroll
                for (int s = 0; s < 2; s++)
                    mma_f16(sf[np * 2 + s], qf[ks], bk[np][2 * s], bk[np][2 * s + 1]);
        }

        const int* kc = (const int*)(sm + AT_MC) + buf * 64;
#pragma unroll
        for (int j = 0; j < 8; j++) {
            int c0 = j * 8 + colb, c1 = c0 + 1;
            int kp0 = k0 + c0, kp1 = k0 + c1;
            int kc0 = kc[c0], kc1 = kc[c1];
            if (!(kp0 <= qr0 && kc0 == qseg0)) sf[j][0] = -1e30f;
            if (!(kp1 <= qr0 && kc1 == qseg0)) sf[j][1] = -1e30f;
            if (!(kp0 <= qr1 && kc0 == qseg1)) sf[j][2] = -1e30f;
            if (!(kp1 <= qr1 && kc1 == qseg1)) sf[j][3] = -1e30f;
        }

        float mx0 = -1e30f, mx1 = -1e30f;
#pragma unroll
        for (int j = 0; j < 8; j++) {
            mx0 = fmaxf(mx0, fmaxf(sf[j][0], sf[j][1]));
            mx1 = fmaxf(mx1, fmaxf(sf[j][2], sf[j][3]));
        }
        mx0 = fmaxf(mx0, __shfl_xor_sync(0xffffffffu, mx0, 1));
        mx0 = fmaxf(mx0, __shfl_xor_sync(0xffffffffu, mx0, 2));
        mx1 = fmaxf(mx1, __shfl_xor_sync(0xffffffffu, mx1, 1));
        mx1 = fmaxf(mx1, __shfl_xor_sync(0xffffffffu, mx1, 2));
        float mn0 = fmaxf(m0, mx0), mn1 = fmaxf(m1, mx1);
        float a0 = exp2f(m0 - mn0), a1 = exp2f(m1 - mn1);
        m0 = mn0; m1 = mn1;
        float s0 = 0.f, s1 = 0.f;
#pragma unroll
        for (int j = 0; j < 8; j++) {
            sf[j][0] = exp2f(sf[j][0] - mn0);
            sf[j][1] = exp2f(sf[j][1] - mn0);
            sf[j][2] = exp2f(sf[j][2] - mn1);
            sf[j][3] = exp2f(sf[j][3] - mn1);
            s0 += sf[j][0] + sf[j][1];
            s1 += sf[j][2] + sf[j][3];
        }
        s0 += __shfl_xor_sync(0xffffffffu, s0, 1);
        s0 += __shfl_xor_sync(0xffffffffu, s0, 2);
        s1 += __shfl_xor_sync(0xffffffffu, s1, 1);
        s1 += __shfl_xor_sync(0xffffffffu, s1, 2);
        l0 = l0 * a0 + s0;
        l1 = l1 * a1 + s1;
#pragma unroll
        for (int j = 0; j < 16; j++) {
            o[j][0] *= a0; o[j][1] *= a0;
            o[j][2] *= a1; o[j][3] *= a1;
        }

        uint32_t pa[4][4];
#pragma unroll
        for (int kk = 0; kk < 4; kk++) {
            pa[kk][0] = h2_as_u32(__floats2half2_rn(sf[2 * kk][0], sf[2 * kk][1]));
            pa[kk][1] = h2_as_u32(__floats2half2_rn(sf[2 * kk][2], sf[2 * kk][3]));
            pa[kk][2] = h2_as_u32(__floats2half2_rn(sf[2 * kk + 1][0], sf[2 * kk + 1][1]));
            pa[kk][3] = h2_as_u32(__floats2half2_rn(sf[2 * kk + 1][2], sf[2 * kk + 1][3]));
        }

        const uint32_t vb = sb + AT_V + buf * AT_KB;
#pragma unroll
        for (int ks = 0; ks < 4; ks++) {
            uint32_t bv[8][4];
#pragma unroll
            for (int nb = 0; nb < 8; nb++) {
                uint32_t addr = vb + (ks * 16 + (lane & 15)) * ATSTR +
                                (nb * 16 + (lane >> 4) * 8) * 2;
                ldm_x4_t(bv[nb], addr);
            }
#pragma unroll
            for (int nb = 0; nb < 8; nb++)
#pragma unroll
                for (int s = 0; s < 2; s++)
                    mma_f16(o[nb * 2 + s], pa[ks], bv[nb][2 * s], bv[nb][2 * s + 1]);
        }
        __syncthreads();
    }

    float inv0 = (l0 > 0.f) ? 1.f / l0 : 0.f;
    float inv1 = (l1 > 0.f) ? 1.f / l1 : 0.f;
#pragma unroll
    for (int j = 0; j < 16; j++) {
        int col = h * HD + j * 8 + colb;
        *(__half2*)(g_Ah + (size_t)qr0 * 2048 + col) =
            __floats2half2_rn(o[j][0] * inv0, o[j][1] * inv0);
        *(__half2*)(g_Ah + (size_t)qr1 * 2048 + col) =
            __floats2half2_rn(o[j][2] * inv1, o[j][3] * inv1);
    }
}

// ---------------------------------------------------------------------------
// Host launcher
// ---------------------------------------------------------------------------
extern "C" void kernel_launch(void* const* d_in, const int* in_sizes, int n_in,
                              void* d_out, int out_size)
{
    const float* X     = (const float*)d_in[0];
    const int*   amask = (const int*)d_in[1];
    const int*   segs  = (const int*)d_in[2];
    const int*   pos   = (const int*)d_in[3];
    const float* Wq    = (const float*)d_in[4];
    const float* Wk    = (const float*)d_in[5];
    const float* Wv    = (const float*)d_in[6];
    const float* Wo    = (const float*)d_in[7];
    float* out = (float*)d_out;

    const int S   = in_sizes[3];
    const int H   = in_sizes[0] / S;        // 2048

    __half *Ah, *Bh;
    cudaGetSymbolAddress((void**)&Ah, g_Ah);
    cudaGetSymbolAddress((void**)&Bh, g_Bh);

    const int smem64  = 3 * (16384 + 64 * 128);    // 73728
    const int smem128 = 3 * (16384 + 128 * 128);   // 98304
    cudaFuncSetAttribute(gemm_mma<64, 128, 3>,
                         cudaFuncAttributeMaxDynamicSharedMemorySize, smem64);
    cudaFuncSetAttribute(gemm_mma<128, 256, 2>,
                         cudaFuncAttributeMaxDynamicSharedMemorySize, smem128);
    cudaFuncSetAttribute(attn_mma, cudaFuncAttributeMaxDynamicSharedMemorySize,
                         AT_SMEM);

    const int n4 = (S * H) / 4;
    cvt_h<<<(n4 + 255) / 256, 256>>>(X, Ah, n4);
    cvt_T_h3<<<dim3(3072 / 32, H / 32), dim3(32, 8)>>>(Wq, Wk, Wv);
    rope_tab<<<(S * 64 + 255) / 256, 256>>>(pos, S);

    // fused QKV GEMM (BN=64, 3 CTAs/SM) with rope/fp16 epilogue
    gemm_mma<64, 128, 3><<<dim3(3072 / 64, S / 128), 128, smem64>>>(nullptr, 3072, 1);

    // Wo conversion (independent; before attention)
    cvt_T_h<<<dim3(H / 32, H / 32), dim3(32, 8)>>>(Wo, Bh, H, H);

    // fp16 flash attention, 2 heads/CTA (writes fp16 A to g_Ah)
    attn_mma<<<dim3(S / 64, NH / 2), 256, AT_SMEM>>>(amask, segs);

    // out = A @ Wo / 256  (BN=128, single wave)
    gemm_mma<128, 256, 2><<<dim3(H / 128, S / 128), 256, smem128>>>(out, H, 0);
}

// round 14
// speedup vs baseline: 1.3181x; 1.3181x over previous
#include <cuda_runtime.h>
#include <cuda_bf16.h>
#include <cuda_fp16.h>
#include <math.h>
#include <stdint.h>

#define NH   16
#define NKV  4
#define HD   128
#define SMAX 2048
#define KDIM 2048

// ---------------- scratch (device globals; no allocation allowed) ----------
__device__ __align__(256) __half g_Ah[SMAX * KDIM];
__device__ __align__(256) __half g_Bh[3072 * KDIM];
__device__ __align__(256) __half g_Bo[KDIM * KDIM];
__device__ __align__(256) __half h_Q[SMAX * NH * HD];
__device__ __align__(256) __half h_K[SMAX * NKV * HD];
__device__ __align__(256) __half h_V[SMAX * NKV * HD];
__device__ __align__(256) float2 g_rope[SMAX * 64];

#define WSCALE 256.0f
#define INVW   0.00390625f

// ---------------- helpers --------------------------------------------------
__device__ __forceinline__ uint32_t smem_u32(const void* p) {
    uint32_t a;
    asm("{ .reg .u64 t; cvta.to.shared.u64 t, %1; cvt.u32.u64 %0, t; }"
        : "=r"(a) : "l"(p));
    return a;
}
__device__ __forceinline__ uint32_t h2_as_u32(__half2 h) {
    return *reinterpret_cast<uint32_t*>(&h);
}
__device__ __forceinline__ void ldm_x4(uint32_t* r, uint32_t addr) {
    asm volatile("ldmatrix.sync.aligned.m8n8.x4.shared.b16 {%0,%1,%2,%3}, [%4];"
                 : "=r"(r[0]), "=r"(r[1]), "=r"(r[2]), "=r"(r[3]) : "r"(addr));
}
__device__ __forceinline__ void ldm_x4_t(uint32_t* r, uint32_t addr) {
    asm volatile("ldmatrix.sync.aligned.m8n8.x4.trans.shared.b16 {%0,%1,%2,%3}, [%4];"
                 : "=r"(r[0]), "=r"(r[1]), "=r"(r[2]), "=r"(r[3]) : "r"(addr));
}
__device__ __forceinline__ void mma_f16(float* d, const uint32_t* a,
                                        uint32_t b0, uint32_t b1) {
    asm volatile(
        "mma.sync.aligned.m16n8k16.row.col.f32.f16.f16.f32 "
        "{%0,%1,%2,%3}, {%4,%5,%6,%7}, {%8,%9}, {%0,%1,%2,%3};"
        : "+f"(d[0]), "+f"(d[1]), "+f"(d[2]), "+f"(d[3])
        : "r"(a[0]), "r"(a[1]), "r"(a[2]), "r"(a[3]), "r"(b0), "r"(b1));
}
__device__ __forceinline__ void cp_async16(uint32_t dst, const void* src) {
    asm volatile("cp.async.cg.shared.global [%0], [%1], 16;"
                 :: "r"(dst), "l"(src) : "memory");
}
#define CP_COMMIT() asm volatile("cp.async.commit_group;" ::: "memory")
#define CP_WAIT0()  asm volatile("cp.async.wait_group 0;" ::: "memory")
#define CP_WAIT1()  asm volatile("cp.async.wait_group 1;" ::: "memory")

// ---------------------------------------------------------------------------
// fp16 GEMM via mma.sync, templated on CTA N-tile (at HMMA f32-accum roofline).
//   BN=64 : 128 threads (4 warps, 2x2 of 64x32), 3 CTAs/SM  (QKV)
//   BN=128: 256 threads (8 warps, 2x4 of 64x32), 2 CTAs/SM  (Wo)
// ---------------------------------------------------------------------------
#define NC (KDIM / 64)

template <int BN, int NTHREADS, int MINCTA>
__global__ __launch_bounds__(NTHREADS, MINCTA) void gemm_mma(
    const __half* __restrict__ B, float* __restrict__ C, int N, int qkv)
{
    constexpr int STAGEB = 16384 + BN * 128;
    constexpr int OFF_B  = 16384;
    extern __shared__ char smem[];
    const uint32_t sb = smem_u32(smem);
    const int tid = threadIdx.x, lane = tid & 31, wid = tid >> 5;
    const int m0 = blockIdx.y * 128, n0 = blockIdx.x * BN;
    const int wm = (BN == 64) ? (wid >> 1) * 64 : (wid >> 2) * 64;
    const int wn = (BN == 64) ? (wid & 1) * 32  : (wid & 3) * 32;

    auto load_chunk = [&](int c, int buf) {
        uint32_t base = sb + buf * STAGEB;
#pragma unroll
        for (int it = 0; it < 16384 / (16 * NTHREADS); it++) {
            int idx = tid + it * NTHREADS;
            int row = idx >> 3, ch = idx & 7;
            cp_async16(base + row * 128 + ((ch ^ (row & 7)) << 4),
                       g_Ah + (size_t)(m0 + row) * KDIM + c * 64 + ch * 8);
        }
#pragma unroll
        for (int it = 0; it < (BN * 128) / (16 * NTHREADS); it++) {
            int idx = tid + it * NTHREADS;
            int row = idx >> 3, ch = idx & 7;
            cp_async16(base + OFF_B + row * 128 + ((ch ^ (row & 7)) << 4),
                       B + (size_t)(n0 + row) * KDIM + c * 64 + ch * 8);
        }
        CP_COMMIT();
    };

    const int arow = wm + (lane & 15);
    const int cA   = lane >> 4;
    const int brow = wn + ((lane >> 4) << 3) + (lane & 7);
    const int cB   = (lane >> 3) & 1;

    float d[4][4][4];
#pragma unroll
    for (int i = 0; i < 4; i++)
#pragma unroll
        for (int j = 0; j < 4; j++)
#pragma unroll
            for (int k = 0; k < 4; k++) d[i][j][k] = 0.f;

    load_chunk(0, 0);
    load_chunk(1, 1);

    for (int c = 0; c < NC; c++) {
        if (c < NC - 1) CP_WAIT1(); else CP_WAIT0();
        __syncthreads();
        if (c + 2 < NC) load_chunk(c + 2, (c + 2) % 3);

        const uint32_t base = sb + (c % 3) * STAGEB;
#pragma unroll
        for (int ks = 0; ks < 4; ks++) {
            uint32_t a[4][4], b[2][4];
#pragma unroll
            for (int mt = 0; mt < 4; mt++) {
                int row = arow + mt * 16;
                ldm_x4(a[mt], base + row * 128 + (((ks * 2 + cA) ^ (row & 7)) << 4));
            }
#pragma unroll
            for (int np = 0; np < 2; np++) {
                int row = brow + np * 16;
                ldm_x4(b[np], base + OFF_B + row * 128 +
                              (((ks * 2 + cB) ^ (row & 7)) << 4));
            }
#pragma unroll
            for (int mt = 0; mt < 4; mt++)
#pragma unroll
                for (int np = 0; np < 2; np++)
#pragma unroll
                    for (int s = 0; s < 2; s++)
                        mma_f16(d[mt][np * 2 + s], a[mt],
                                b[np][2 * s], b[np][2 * s + 1]);
        }
        __syncthreads();
    }

    const int colb = (lane & 3) * 2;
    if (!qkv) {
#pragma unroll
        for (int mt = 0; mt < 4; mt++) {
            int r = m0 + wm + mt * 16 + (lane >> 2);
#pragma unroll
            for (int nt = 0; nt < 4; nt++) {
                int col = n0 + wn + nt * 8 + colb;
                *(float2*)(C + (size_t)r * N + col) =
                    make_float2(d[mt][nt][0] * INVW, d[mt][nt][1] * INVW);
                *(float2*)(C + (size_t)(r + 8) * N + col) =
                    make_float2(d[mt][nt][2] * INVW, d[mt][nt][3] * INVW);
            }
        }
    } else {
        const int mode = (n0 < 2048) ? 0 : (n0 < 2560 ? 1 : 2);
        // Q scale includes 1/sqrt(hd) * log2(e) so attention can use exp2f
        const float qs = 0.0883883476483184f * 1.4426950408889634f * INVW;
#pragma unroll
        for (int mt = 0; mt < 4; mt++) {
            int r = m0 + wm + mt * 16 + (lane >> 2);
#pragma unroll
            for (int nt = 0; nt < 4; nt++) {
                int col = n0 + wn + nt * 8 + colb;
                float c00 = d[mt][nt][0], c01 = d[mt][nt][1];
                float c10 = d[mt][nt][2], c11 = d[mt][nt][3];
                if (mode == 2) {
                    int cv = col - 2560;
                    *(__half2*)(h_V + (size_t)r * 512 + cv) =
                        __floats2half2_rn(c00 * INVW, c01 * INVW);
                    *(__half2*)(h_V + (size_t)(r + 8) * 512 + cv) =
                        __floats2half2_rn(c10 * INVW, c11 * INVW);
                } else {
                    int cl = (mode == 0) ? col : col - 2048;
                    int i = (cl & 127) >> 1;
                    float2 t0 = g_rope[r * 64 + i];
                    float2 t1 = g_rope[(r + 8) * 64 + i];
                    float s = (mode == 0) ? qs : INVW;
                    float o00 = (c00 * t0.x - c01 * t0.y) * s;
                    float o01 = (c00 * t0.y + c01 * t0.x) * s;
                    float o10 = (c10 * t1.x - c11 * t1.y) * s;
                    float o11 = (c10 * t1.y + c11 * t1.x) * s;
                    if (mode == 0) {
                        *(__half2*)(h_Q + (size_t)r * 2048 + cl)       = __floats2half2_rn(o00, o01);
                        *(__half2*)(h_Q + (size_t)(r + 8) * 2048 + cl) = __floats2half2_rn(o10, o11);
                    } else {
                        *(__half2*)(h_K + (size_t)r * 512 + cl)       = __floats2half2_rn(o00, o01);
                        *(__half2*)(h_K + (size_t)(r + 8) * 512 + cl) = __floats2half2_rn(o10, o11);
                    }
                }
            }
        }
    }
}

// ---------------------------------------------------------------------------
// Merged prep kernel: one launch does
//   [0, 4096)        : X fp32 -> fp16 (g_Ah)
//   [4096, 10240)    : Wq|Wk|Wv transpose+convert (x256) -> g_Bh[3072][2048]
//   [10240, 14336)   : Wo transpose+convert (x256)       -> g_Bo[2048][2048]
//   [14336, 14848)   : rope table
// ---------------------------------------------------------------------------
#define PB_X   4096
#define PB_W3  6144
#define PB_WO  4096
#define PB_RT  512

__global__ __launch_bounds__(256) void prep_all(
    const float* __restrict__ X,
    const float* __restrict__ Wq, const float* __restrict__ Wk,
    const float* __restrict__ Wv, const float* __restrict__ Wo,
    const int* __restrict__ pos)
{
    __shared__ float t[32][33];
    const int b = blockIdx.x;
    const int tid = threadIdx.x;
    const int tx = tid & 31, ty = tid >> 5;

    if (b < PB_X) {
        int i = b * 256 + tid;
        float4 v = ((const float4*)X)[i];
        uint2 u;
        u.x = h2_as_u32(__floats2half2_rn(v.x, v.y));
        u.y = h2_as_u32(__floats2half2_rn(v.z, v.w));
        ((uint2*)g_Ah)[i] = u;
    } else if (b < PB_X + PB_W3) {
        int bb = b - PB_X;
        int bx = bb % 96, by = bb / 96;
        int bc = bx * 32;
        const float* W; int n0, Nw;
        if (bc < 2048)      { W = Wq; n0 = 0;    Nw = 2048; }
        else if (bc < 2560) { W = Wk; n0 = 2048; Nw = 512;  }
        else                { W = Wv; n0 = 2560; Nw = 512;  }
        int x = bc - n0 + tx;
        int y = by * 32 + ty;
#pragma unroll
        for (int j = 0; j < 32; j += 8)
            t[ty + j][tx] = W[(size_t)(y + j) * Nw + x];
        __syncthreads();
        int x2 = by * 32 + tx;
        int y2 = bc + ty;
#pragma unroll
        for (int j = 0; j < 32; j += 8)
            g_Bh[(size_t)(y2 + j) * KDIM + x2] =
                __float2half_rn(t[tx][ty + j] * WSCALE);
    } else if (b < PB_X + PB_W3 + PB_WO) {
        int bb = b - (PB_X + PB_W3);
        int bx = bb % 64, by = bb / 64;
        int x = bx * 32 + tx;
        int y = by * 32 + ty;
#pragma unroll
        for (int j = 0; j < 32; j += 8)
            t[ty + j][tx] = Wo[(size_t)(y + j) * KDIM + x];
        __syncthreads();
        int x2 = by * 32 + tx;
        int y2 = bx * 32 + ty;
#pragma unroll
        for (int j = 0; j < 32; j += 8)
            g_Bo[(size_t)(y2 + j) * KDIM + x2] =
                __float2half_rn(t[tx][ty + j] * WSCALE);
    } else {
        int idx = (b - (PB_X + PB_W3 + PB_WO)) * 256 + tid;
        int i = idx & 63, s = idx >> 6;
        float freq = exp2f(-(float)(2 * i) * (1.0f / 128.0f) * 13.287712379549449f);
        float ang = (float)pos[s] * freq;
        float sn, cs;
        sincosf(ang, &sn, &cs);
        g_rope[idx] = make_float2(cs, sn);
    }
}

// ---------------------------------------------------------------------------
// fp16 mma.sync flash attention (base-2 softmax). 128 threads, BQ=64,
// KV tiles of 64, Q staged in K-buffer-1 region; 3 CTAs/SM.
// Epilogue writes fp16 A directly into g_Ah.   (R12 config — validated)
// ---------------------------------------------------------------------------
#define ATSTR 272
#define AT_KB 17408
#define AT_V  34816
#define AT_MC 69632
#define AT_SMEM 70144

__global__ __launch_bounds__(128, 3) void attn_mma(
    const int* __restrict__ amask, const int* __restrict__ segs)
{
    extern __shared__ char sm[];
    const uint32_t sb = smem_u32(sm);
    const int tid = threadIdx.x, lane = tid & 31, wid = tid >> 5;
    const int h = blockIdx.y;
    const int qb = (int)gridDim.x - 1 - (int)blockIdx.x;
    const int q0 = qb * 64;
    const int kvh = h >> 2;
    const int ntile = qb + 1;

    auto prefetch = [&](int t) {
        int k0 = t * 64;
        int buf = t & 1;
#pragma unroll
        for (int it = 0; it < 8; it++) {
            int idx = tid + it * 128;
            int row = idx >> 4, ch = idx & 15;
            cp_async16(sb + buf * AT_KB + row * ATSTR + ch * 16,
                       h_K + ((size_t)(k0 + row) * NKV + kvh) * HD + ch * 8);
            cp_async16(sb + AT_V + buf * AT_KB + row * ATSTR + ch * 16,
                       h_V + ((size_t)(k0 + row) * NKV + kvh) * HD + ch * 8);
        }
        if (tid < 64) {
            int a = amask[k0 + tid];
            ((int*)(sm + AT_MC))[buf * 64 + tid] =
                (a > 0) ? segs[k0 + tid] : 0x7fffffff;
        }
        CP_COMMIT();
    };

#pragma unroll
    for (int it = 0; it < 8; it++) {
        int idx = tid + it * 128;
        int row = idx >> 4, ch = idx & 15;
        cp_async16(sb + AT_KB + row * ATSTR + ch * 16,
                   h_Q + ((size_t)(q0 + row) * NH + h) * HD + ch * 8);
    }
    prefetch(0);
    CP_WAIT0();
    __syncthreads();

    uint32_t qf[8][4];
#pragma unroll
    for (int ks = 0; ks < 8; ks++) {
        uint32_t addr = sb + AT_KB + (wid * 16 + (lane & 15)) * ATSTR +
                        (ks * 16 + (lane >> 4) * 8) * 2;
        ldm_x4(qf[ks], addr);
    }
    __syncthreads();

    const int qr0 = q0 + wid * 16 + (lane >> 2);
    const int qr1 = qr0 + 8;
    const int qseg0 = segs[qr0];
    const int qseg1 = segs[qr1];
    const int colb = (lane & 3) * 2;

    float o[16][4];
#pragma unroll
    for (int j = 0; j < 16; j++)
#pragma unroll
        for (int k = 0; k < 4; k++) o[j][k] = 0.f;
    float m0 = -1e30f, m1 = -1e30f, l0 = 0.f, l1 = 0.f;

    for (int t = 0; t < ntile; t++) {
        const int k0 = t * 64;
        const int buf = t & 1;
        if (t + 1 < ntile) { prefetch(t + 1); CP_WAIT1(); }
        else               { CP_WAIT0(); }
        __syncthreads();

        float sf[8][4];
#pragma unroll
        for (int j = 0; j < 8; j++)
#pragma unroll
            for (int k = 0; k < 4; k++) sf[j][k] = 0.f;

        const uint32_t kb = sb + buf * AT_KB;
#pragma unroll
        for (int ks = 0; ks < 8; ks++) {
            uint32_t bk[4][4];
#pragma unroll
            for (int np = 0; np < 4; np++) {
                uint32_t addr = kb + (np * 16 + ((lane >> 4) << 3) + (lane & 7)) * ATSTR +
                                (ks * 16 + ((lane >> 3) & 1) * 8) * 2;
                ldm_x4(bk[np], addr);
            }
#pragma unroll
            for (int np = 0; np < 4; np++)
#pragma unroll
                for (int s = 0; s < 2; s++)
                    mma_f16(sf[np * 2 + s], qf[ks], bk[np][2 * s], bk[np][2 * s + 1]);
        }

        const int* kc = (const int*)(sm + AT_MC) + buf * 64;
#pragma unroll
        for (int j = 0; j < 8; j++) {
            int c0 = j * 8 + colb, c1 = c0 + 1;
            int kp0 = k0 + c0, kp1 = k0 + c1;
            int kc0 = kc[c0], kc1 = kc[c1];
            if (!(kp0 <= qr0 && kc0 == qseg0)) sf[j][0] = -1e30f;
            if (!(kp1 <= qr0 && kc1 == qseg0)) sf[j][1] = -1e30f;
            if (!(kp0 <= qr1 && kc0 == qseg1)) sf[j][2] = -1e30f;
            if (!(kp1 <= qr1 && kc1 == qseg1)) sf[j][3] = -1e30f;
        }

        float mx0 = -1e30f, mx1 = -1e30f;
#pragma unroll
        for (int j = 0; j < 8; j++) {
            mx0 = fmaxf(mx0, fmaxf(sf[j][0], sf[j][1]));
            mx1 = fmaxf(mx1, fmaxf(sf[j][2], sf[j][3]));
        }
        mx0 = fmaxf(mx0, __shfl_xor_sync(0xffffffffu, mx0, 1));
        mx0 = fmaxf(mx0, __shfl_xor_sync(0xffffffffu, mx0, 2));
        mx1 = fmaxf(mx1, __shfl_xor_sync(0xffffffffu, mx1, 1));
        mx1 = fmaxf(mx1, __shfl_xor_sync(0xffffffffu, mx1, 2));
        float mn0 = fmaxf(m0, mx0), mn1 = fmaxf(m1, mx1);
        float a0 = exp2f(m0 - mn0), a1 = exp2f(m1 - mn1);
        m0 = mn0; m1 = mn1;
        float s0 = 0.f, s1 = 0.f;
#pragma unroll
        for (int j = 0; j < 8; j++) {
            sf[j][0] = exp2f(sf[j][0] - mn0);
            sf[j][1] = exp2f(sf[j][1] - mn0);
            sf[j][2] = exp2f(sf[j][2] - mn1);
            sf[j][3] = exp2f(sf[j][3] - mn1);
            s0 += sf[j][0] + sf[j][1];
            s1 += sf[j][2] + sf[j][3];
        }
        s0 += __shfl_xor_sync(0xffffffffu, s0, 1);
        s0 += __shfl_xor_sync(0xffffffffu, s0, 2);
        s1 += __shfl_xor_sync(0xffffffffu, s1, 1);
        s1 += __shfl_xor_sync(0xffffffffu, s1, 2);
        l0 = l0 * a0 + s0;
        l1 = l1 * a1 + s1;
#pragma unroll
        for (int j = 0; j < 16; j++) {
            o[j][0] *= a0; o[j][1] *= a0;
            o[j][2] *= a1; o[j][3] *= a1;
        }

        uint32_t pa[4][4];
#pragma unroll
        for (int kk = 0; kk < 4; kk++) {
            pa[kk][0] = h2_as_u32(__floats2half2_rn(sf[2 * kk][0], sf[2 * kk][1]));
            pa[kk][1] = h2_as_u32(__floats2half2_rn(sf[2 * kk][2], sf[2 * kk][3]));
            pa[kk][2] = h2_as_u32(__floats2half2_rn(sf[2 * kk + 1][0], sf[2 * kk + 1][1]));
            pa[kk][3] = h2_as_u32(__floats2half2_rn(sf[2 * kk + 1][2], sf[2 * kk + 1][3]));
        }

        const uint32_t vb = sb + AT_V + buf * AT_KB;
#pragma unroll
        for (int ks = 0; ks < 4; ks++) {
            uint32_t bv[8][4];
#pragma unroll
            for (int nb = 0; nb < 8; nb++) {
                uint32_t addr = vb + (ks * 16 + (lane & 15)) * ATSTR +
                                (nb * 16 + (lane >> 4) * 8) * 2;
                ldm_x4_t(bv[nb], addr);
            }
#pragma unroll
            for (int nb = 0; nb < 8; nb++)
#pragma unroll
                for (int s = 0; s < 2; s++)
                    mma_f16(o[nb * 2 + s], pa[ks], bv[nb][2 * s], bv[nb][2 * s + 1]);
        }
        __syncthreads();
    }

    float inv0 = (l0 > 0.f) ? 1.f / l0 : 0.f;
    float inv1 = (l1 > 0.f) ? 1.f / l1 : 0.f;
#pragma unroll
    for (int j = 0; j < 16; j++) {
        int col = h * HD + j * 8 + colb;
        *(__half2*)(g_Ah + (size_t)qr0 * 2048 + col) =
            __floats2half2_rn(o[j][0] * inv0, o[j][1] * inv0);
        *(__half2*)(g_Ah + (size_t)qr1 * 2048 + col) =
            __floats2half2_rn(o[j][2] * inv1, o[j][3] * inv1);
    }
}

// ---------------------------------------------------------------------------
// Host launcher
// ---------------------------------------------------------------------------
extern "C" void kernel_launch(void* const* d_in, const int* in_sizes, int n_in,
                              void* d_out, int out_size)
{
    const float* X     = (const float*)d_in[0];
    const int*   amask = (const int*)d_in[1];
    const int*   segs  = (const int*)d_in[2];
    const int*   pos   = (const int*)d_in[3];
    const float* Wq    = (const float*)d_in[4];
    const float* Wk    = (const float*)d_in[5];
    const float* Wv    = (const float*)d_in[6];
    const float* Wo    = (const float*)d_in[7];
    float* out = (float*)d_out;

    const int S   = in_sizes[3];
    const int H   = in_sizes[0] / S;        // 2048

    __half *Bh, *Bo;
    cudaGetSymbolAddress((void**)&Bh, g_Bh);
    cudaGetSymbolAddress((void**)&Bo, g_Bo);

    const int smem64  = 3 * (16384 + 64 * 128);    // 73728
    const int smem128 = 3 * (16384 + 128 * 128);   // 98304
    cudaFuncSetAttribute(gemm_mma<64, 128, 3>,
                         cudaFuncAttributeMaxDynamicSharedMemorySize, smem64);
    cudaFuncSetAttribute(gemm_mma<128, 256, 2>,
                         cudaFuncAttributeMaxDynamicSharedMemorySize, smem128);
    cudaFuncSetAttribute(attn_mma, cudaFuncAttributeMaxDynamicSharedMemorySize,
                         AT_SMEM);

    // one merged prep launch: X->fp16, W transposes (QKV + Wo), rope table
    prep_all<<<PB_X + PB_W3 + PB_WO + PB_RT, 256>>>(X, Wq, Wk, Wv, Wo, pos);

    // fused QKV GEMM (BN=64, 3 CTAs/SM) with rope/fp16 epilogue
    gemm_mma<64, 128, 3><<<dim3(3072 / 64, S / 128), 128, smem64>>>(Bh, nullptr, 3072, 1);

    // fp16 flash attention (writes fp16 A to g_Ah)
    attn_mma<<<dim3(S / 64, NH), 128, AT_SMEM>>>(amask, segs);

    // out = A @ Wo / 256  (BN=128, single wave)
    gemm_mma<128, 256, 2><<<dim3(H / 128, S / 128), 256, smem128>>>(Bo, out, H, 0);
}